// round 3
// baseline (speedup 1.0000x reference)
#include <cuda_runtime.h>
#include <math.h>

typedef unsigned long long u64;

#define C_DIM 2048
#define E_DIM 64
#define TM    64
#define KT    16
#define NTHR  128
#define NKT   (C_DIM / KT)
#define ASTR  68
#define BSTR  68
#define AMB_CAP 65536
#define TAU   1e-5f

__device__ float g_colinv[E_DIM];
__device__ unsigned g_amb_count;
__device__ unsigned g_amb_list[AMB_CAP];

__device__ __forceinline__ u64 pack_dup(float v) {
    u64 d;
    asm("mov.b64 %0, {%1, %1};" : "=l"(d) : "r"(__float_as_uint(v)));
    return d;
}
__device__ __forceinline__ void fma2(u64& d, u64 a, u64 b) {
    asm("fma.rn.f32x2 %0, %1, %2, %0;" : "+l"(d) : "l"(a), "l"(b));
}
__device__ __forceinline__ float lo32(u64 v) { return __uint_as_float((unsigned)v); }
__device__ __forceinline__ float hi32(u64 v) { return __uint_as_float((unsigned)(v >> 32)); }

// ---------------------------------------------------------------------------
// Kernel 1: reciprocal column norms of sim_matrix (C x E). Also resets the
// ambiguous-entry counter (block 0).
// ---------------------------------------------------------------------------
__global__ void colnorm_kernel(const float* __restrict__ sim) {
    if (blockIdx.x == 0 && threadIdx.x == 0) g_amb_count = 0;
    int e = blockIdx.x;
    float s = 0.f;
    for (int c = threadIdx.x; c < C_DIM; c += 128) {
        float v = sim[c * E_DIM + e];
        s = fmaf(v, v, s);
    }
#pragma unroll
    for (int off = 16; off; off >>= 1) s += __shfl_xor_sync(0xffffffffu, s, off);
    __shared__ float red[4];
    if ((threadIdx.x & 31) == 0) red[threadIdx.x >> 5] = s;
    __syncthreads();
    if (threadIdx.x == 0) {
        float t = red[0] + red[1] + red[2] + red[3];
        g_colinv[e] = 1.0f / fmaxf(sqrtf(t), 1e-12f);
    }
}

// ---------------------------------------------------------------------------
// Kernel 2: fused gating GEMM + normalization + mask epilogue.
//   64x64 tile, 128 threads, 8x4 micro-tile as packed f32x2 accumulators.
//   Flags |z| < TAU entries for fp64 refinement.
// ---------------------------------------------------------------------------
__global__ __launch_bounds__(NTHR)
void gating_kernel(const float* __restrict__ x,
                   const float* __restrict__ sim,
                   const float* __restrict__ gates,
                   const float* __restrict__ temp,
                   const float* __restrict__ emask,
                   const int*   __restrict__ minkp,
                   float* __restrict__ out,
                   int N)
{
    __shared__ float Ast[KT][ASTR];          // [k][row], padded
    __shared__ float Bs [KT][BSTR];          // [k][expert], padded
    __shared__ float rowinvS[TM];
    __shared__ float colinvS[E_DIM];
    __shared__ float gthS[E_DIM];
    __shared__ float emS[E_DIM];
    __shared__ float Lg[TM][E_DIM + 1];      // logits (masked)
    __shared__ float Mk[TM][E_DIM + 1];      // activation mask

    const int tid  = threadIdx.x;
    const int row0 = blockIdx.x * TM;

    if (tid < E_DIM) {
        colinvS[tid] = g_colinv[tid];
        emS[tid]     = emask[tid];
        float t      = temp[0];
        float scale  = 1.0f / (1.0f + expf(-t));
        gthS[tid]    = gates[tid] * scale;
    }

    // --- loader mappings ---
    const int arowL = tid >> 1;              // local row 0..63 (2 threads/row)
    const int kHalf = (tid & 1) * 8;         // which 8 k's of the 16-k tile
    const long arow = (long)min(row0 + arowL, N - 1);
    const float* aptr = x + arow * (long)C_DIM + kHalf;

    const int kB = tid >> 3;                 // k row of B tile, 0..15
    const int cB = (tid & 7) * 8;            // expert offset
    const float* bptr = sim + (long)kB * E_DIM + cB;

    // --- compute mapping ---
    const int tx = tid & 15;                 // expert group (4 experts)
    const int ty = tid >> 4;                 // row group (8 rows)

    u64 acc[4][4];
#pragma unroll
    for (int i = 0; i < 4; ++i)
#pragma unroll
        for (int j = 0; j < 4; ++j) acc[i][j] = 0ull;

    // prologue load of tile 0
    float4 a0 = *(const float4*)(aptr);
    float4 a1 = *(const float4*)(aptr + 4);
    float4 b0 = *(const float4*)(bptr);
    float4 b1 = *(const float4*)(bptr + 4);

    float sumsq = 0.f;

    for (int kt = 0; kt < NKT; ++kt) {
        __syncthreads();                     // previous compute done
        // store A (transposed) + accumulate row sum of squares
        Ast[kHalf + 0][arowL] = a0.x;
        Ast[kHalf + 1][arowL] = a0.y;
        Ast[kHalf + 2][arowL] = a0.z;
        Ast[kHalf + 3][arowL] = a0.w;
        Ast[kHalf + 4][arowL] = a1.x;
        Ast[kHalf + 5][arowL] = a1.y;
        Ast[kHalf + 6][arowL] = a1.z;
        Ast[kHalf + 7][arowL] = a1.w;
        sumsq = fmaf(a0.x, a0.x, sumsq); sumsq = fmaf(a0.y, a0.y, sumsq);
        sumsq = fmaf(a0.z, a0.z, sumsq); sumsq = fmaf(a0.w, a0.w, sumsq);
        sumsq = fmaf(a1.x, a1.x, sumsq); sumsq = fmaf(a1.y, a1.y, sumsq);
        sumsq = fmaf(a1.z, a1.z, sumsq); sumsq = fmaf(a1.w, a1.w, sumsq);
        *(float4*)&Bs[kB][cB]     = b0;
        *(float4*)&Bs[kB][cB + 4] = b1;
        __syncthreads();                     // tile visible

        if (kt + 1 < NKT) {                  // prefetch next tile into regs
            const float* ap = aptr + (kt + 1) * KT;
            a0 = *(const float4*)ap;
            a1 = *(const float4*)(ap + 4);
            const float* bp = bptr + (size_t)(kt + 1) * KT * E_DIM;
            b0 = *(const float4*)bp;
            b1 = *(const float4*)(bp + 4);
        }

#pragma unroll
        for (int k = 0; k < KT; ++k) {
            ulonglong2 aL = *(const ulonglong2*)&Ast[k][ty * 8];
            ulonglong2 aH = *(const ulonglong2*)&Ast[k][ty * 8 + 4];
            float4 bf = *(const float4*)&Bs[k][tx * 4];
            u64 bb0 = pack_dup(bf.x);
            u64 bb1 = pack_dup(bf.y);
            u64 bb2 = pack_dup(bf.z);
            u64 bb3 = pack_dup(bf.w);
            fma2(acc[0][0], aL.x, bb0); fma2(acc[0][1], aL.x, bb1);
            fma2(acc[0][2], aL.x, bb2); fma2(acc[0][3], aL.x, bb3);
            fma2(acc[1][0], aL.y, bb0); fma2(acc[1][1], aL.y, bb1);
            fma2(acc[1][2], aL.y, bb2); fma2(acc[1][3], aL.y, bb3);
            fma2(acc[2][0], aH.x, bb0); fma2(acc[2][1], aH.x, bb1);
            fma2(acc[2][2], aH.x, bb2); fma2(acc[2][3], aH.x, bb3);
            fma2(acc[3][0], aH.y, bb0); fma2(acc[3][1], aH.y, bb1);
            fma2(acc[3][2], aH.y, bb2); fma2(acc[3][3], aH.y, bb3);
        }
    }

    // --- row norms: thread pair (tid, tid^1) shares a row ---
    sumsq += __shfl_xor_sync(0xffffffffu, sumsq, 1);
    if ((tid & 1) == 0)
        rowinvS[arowL] = 1.0f / fmaxf(sqrtf(sumsq), 1e-12f);
    __syncthreads();

    // --- normalized + masked logits into smem ---
#pragma unroll
    for (int rp = 0; rp < 4; ++rp) {
        int r0 = ty * 8 + rp * 2;
        float ri0 = rowinvS[r0];
        float ri1 = rowinvS[r0 + 1];
#pragma unroll
        for (int c = 0; c < 4; ++c) {
            int col = tx * 4 + c;
            float f = colinvS[col] * emS[col];
            Lg[r0    ][col] = lo32(acc[rp][c]) * ri0 * f;
            Lg[r0 + 1][col] = hi32(acc[rp][c]) * ri1 * f;
        }
    }
    __syncthreads();

    // --- per-row mask + ambiguity flagging + top-k fallback ---
    int minK = minkp ? *minkp : 2;
    minK = min(max(minK, 0), E_DIM);
    if (tid < TM) {
        const int row = tid;
        const int grow = row0 + row;
        float cnt = 0.f;
#pragma unroll
        for (int e = 0; e < E_DIM; ++e) {
            float z = Lg[row][e] - gthS[e];
            float m = (z > 0.f) ? 1.0f : 0.0f;
            cnt += m;
            Mk[row][e] = m;
            if (fabsf(z) < TAU && grow < N) {   // near the decision boundary:
                unsigned idx = atomicAdd(&g_amb_count, 1u);
                if (idx < AMB_CAP)
                    g_amb_list[idx] = ((unsigned)grow << 8) | (unsigned)e;
            }
        }
        if (cnt == 0.f) {                    // cold path: fallback top-k
            for (int kk = 0; kk < minK; ++kk) {
                float best = -3.402823466e38f;
                int bi = -1;
                for (int e = 0; e < E_DIM; ++e) {
                    if (Mk[row][e] == 0.f && Lg[row][e] > best) {
                        best = Lg[row][e];
                        bi = e;
                    }
                }
                if (bi >= 0) Mk[row][bi] = 1.0f;
            }
        }
    }
    __syncthreads();

    // --- cooperative coalesced stores: mask at [0, N*E), logits at [N*E, 2N*E) ---
    const size_t NE = (size_t)N * E_DIM;
#pragma unroll
    for (int j = 0; j < (TM * E_DIM) / (4 * NTHR); ++j) {   // 8 iters
        int f4  = tid + j * NTHR;
        int row = f4 >> 4;
        int cc  = (f4 & 15) * 4;
        int grow = row0 + row;
        if (grow < N) {
            float4 mv = make_float4(Mk[row][cc], Mk[row][cc + 1],
                                    Mk[row][cc + 2], Mk[row][cc + 3]);
            float4 lv = make_float4(Lg[row][cc], Lg[row][cc + 1],
                                    Lg[row][cc + 2], Lg[row][cc + 3]);
            *(float4*)&out[(size_t)grow * E_DIM + cc]      = mv;
            *(float4*)&out[NE + (size_t)grow * E_DIM + cc] = lv;
        }
    }
}

// ---------------------------------------------------------------------------
// Kernel 3: fp64 refinement of ambiguous mask entries. One warp per entry.
// Decides the TRUE sign of (normalized logit - gate threshold).
// ---------------------------------------------------------------------------
__global__ __launch_bounds__(128)
void refine_kernel(const float* __restrict__ x,
                   const float* __restrict__ sim,
                   const float* __restrict__ gates,
                   const float* __restrict__ temp,
                   const float* __restrict__ emask,
                   float* __restrict__ out)
{
    unsigned cnt = g_amb_count;
    if (cnt > AMB_CAP) cnt = AMB_CAP;
    const int lane  = threadIdx.x & 31;
    const int warp  = (blockIdx.x * blockDim.x + threadIdx.x) >> 5;
    const int nwarp = (gridDim.x * blockDim.x) >> 5;

    for (unsigned i = warp; i < cnt; i += nwarp) {
        unsigned pk = g_amb_list[i];
        int r = (int)(pk >> 8);
        int e = (int)(pk & 0xFF);
        const float* ar = x + (size_t)r * C_DIM;
        double d = 0.0, na = 0.0, nb = 0.0;
        for (int k = lane; k < C_DIM; k += 32) {
            double av = (double)ar[k];
            double bv = (double)sim[(size_t)k * E_DIM + e];
            d  = fma(av, bv, d);
            na = fma(av, av, na);
            nb = fma(bv, bv, nb);
        }
#pragma unroll
        for (int off = 16; off; off >>= 1) {
            d  += __shfl_xor_sync(0xffffffffu, d,  off);
            na += __shfl_xor_sync(0xffffffffu, na, off);
            nb += __shfl_xor_sync(0xffffffffu, nb, off);
        }
        if (lane == 0) {
            double t     = (double)temp[0];
            double scale = 1.0 / (1.0 + exp(-t));
            double lg = d / fmax(sqrt(na), 1e-12) / fmax(sqrt(nb), 1e-12);
            lg *= (double)emask[e];
            double z = lg - (double)gates[e] * scale;
            out[(size_t)r * E_DIM + e] = (z > 0.0) ? 1.0f : 0.0f;
        }
    }
}

extern "C" void kernel_launch(void* const* d_in, const int* in_sizes, int n_in,
                              void* d_out, int out_size) {
    (void)out_size;
    const float* x     = (const float*)d_in[0];
    const float* sim   = (const float*)d_in[1];
    const float* gates = (const float*)d_in[2];
    const float* temp  = (const float*)d_in[3];
    const float* emask = (const float*)d_in[4];
    const int*   minkp = (n_in > 5) ? (const int*)d_in[5] : nullptr;

    int N = in_sizes[0] / C_DIM;

    colnorm_kernel<<<E_DIM, 128>>>(sim);
    int grid = (N + TM - 1) / TM;
    gating_kernel<<<grid, NTHR>>>(x, sim, gates, temp, emask, minkp,
                                  (float*)d_out, N);
    refine_kernel<<<128, 128>>>(x, sim, gates, temp, emask, (float*)d_out);
}